// round 1
// baseline (speedup 1.0000x reference)
#include <cuda_runtime.h>

// AvgNeighbor / COO SpMM:
//   out[r, :] += vals[e] * seq[cols[e], :]  for each edge e with rows[e] == r
// rows is sorted -> segmented accumulation in registers, atomic flush only on
// row transitions and chunk boundaries.
//
// Inputs (metadata order): seq [1*50000*64 f32], vals [E f32], rows [E i32], cols [E i32]
// Output: [1, 50000, 64] f32

#define D_FEAT 64
#define EDGES_PER_WARP 128
#define WARPS_PER_BLOCK 8
#define EDGES_PER_BLOCK (EDGES_PER_WARP * WARPS_PER_BLOCK)  // 1024
#define BLOCK_THREADS (WARPS_PER_BLOCK * 32)                // 256

__global__ void zero_out_kernel(float4* __restrict__ out, int n4) {
    int i = blockIdx.x * blockDim.x + threadIdx.x;
    if (i < n4) out[i] = make_float4(0.f, 0.f, 0.f, 0.f);
}

__global__ __launch_bounds__(BLOCK_THREADS)
void spmm_seg_kernel(const float* __restrict__ seq,
                     const float* __restrict__ vals,
                     const int* __restrict__ rows,
                     const int* __restrict__ cols,
                     float* __restrict__ out,
                     int n_edges) {
    __shared__ int   s_rows[EDGES_PER_BLOCK];
    __shared__ int   s_cols[EDGES_PER_BLOCK];
    __shared__ float s_vals[EDGES_PER_BLOCK];

    const int base = blockIdx.x * EDGES_PER_BLOCK;
    const int n    = min(EDGES_PER_BLOCK, n_edges - base);
    if (n <= 0) return;

    // Cooperative coalesced staging of this block's edge metadata.
    for (int i = threadIdx.x; i < n; i += BLOCK_THREADS) {
        s_rows[i] = rows[base + i];
        s_cols[i] = cols[base + i];
        s_vals[i] = vals[base + i];
    }
    __syncthreads();

    const int warp = threadIdx.x >> 5;
    const int lane = threadIdx.x & 31;
    const int wbeg = warp * EDGES_PER_WARP;
    if (wbeg >= n) return;
    const int wend = min(wbeg + EDGES_PER_WARP, n);

    const float2* __restrict__ seq2 = reinterpret_cast<const float2*>(seq);

    float2 acc = make_float2(0.f, 0.f);
    int cur_row = s_rows[wbeg];

    #pragma unroll 4
    for (int i = wbeg; i < wend; ++i) {
        const int r = s_rows[i];          // warp-uniform
        if (r != cur_row) {               // warp-uniform branch, no divergence
            atomicAdd(&out[cur_row * D_FEAT + 2 * lane],     acc.x);
            atomicAdd(&out[cur_row * D_FEAT + 2 * lane + 1], acc.y);
            acc = make_float2(0.f, 0.f);
            cur_row = r;
        }
        const float  v = s_vals[i];
        const float2 x = seq2[(long)s_cols[i] * (D_FEAT / 2) + lane];  // 256B/warp, 1 L2 line
        acc.x = fmaf(v, x.x, acc.x);
        acc.y = fmaf(v, x.y, acc.y);
    }
    // Final flush (row may continue into the next warp's chunk -> atomic).
    atomicAdd(&out[cur_row * D_FEAT + 2 * lane],     acc.x);
    atomicAdd(&out[cur_row * D_FEAT + 2 * lane + 1], acc.y);
}

extern "C" void kernel_launch(void* const* d_in, const int* in_sizes, int n_in,
                              void* d_out, int out_size) {
    const float* seq  = (const float*)d_in[0];
    const float* vals = (const float*)d_in[1];
    const int*   rows = (const int*)d_in[2];
    const int*   cols = (const int*)d_in[3];
    float*       out  = (float*)d_out;
    const int n_edges = in_sizes[1];

    // Zero the (poisoned) output first.
    const int n4 = out_size / 4;
    zero_out_kernel<<<(n4 + 255) / 256, 256>>>((float4*)out, n4);

    const int n_blocks = (n_edges + EDGES_PER_BLOCK - 1) / EDGES_PER_BLOCK;
    spmm_seg_kernel<<<n_blocks, BLOCK_THREADS>>>(seq, vals, rows, cols, out, n_edges);
}